// round 2
// baseline (speedup 1.0000x reference)
#include <cuda_runtime.h>
#include <cuda_bf16.h>
#include <cstdint>

// ---------------------------------------------------------------------------
// VectorQuantizer: z[8,256,32,32] fp32, embedding[16384,256] fp32
// out = [ z_q_out (2,097,152) | loss (1) | idx-as-float (8192) ]  fp32
//
// Distance sweep is a fused GEMM-argmin: d = (||z||^2 + ||e||^2) - 2 z.e
// computed with the reference's exact fp32 formula shape so the quantized
// ties (ulp(256) ~ 3e-5) resolve identically (first-index tie-break).
// Main kernel: 128x128 tile, 8x8/thread, packed fma.rn.f32x2 (FFMA2).
// ---------------------------------------------------------------------------

#define NROWS   8192
#define NCODES  16384
#define DIM     256
#define NSPLIT  2
#define CODES_PER_SPLIT (NCODES / NSPLIT)
#define MT      128
#define NT      128
#define KC      32

#define NZQ      2097152     // 8*256*32*32
#define OFF_LOSS NZQ
#define OFF_IDX  (NZQ + 1)

// ---- device scratch (no allocations allowed) ----
__device__ float g_zflat[NROWS * DIM];          // 8 MB: z as [row][dim]
__device__ float g_znorm[NROWS];
__device__ float g_enorm[NCODES];
__device__ float g_cand_d[NSPLIT * NROWS];
__device__ int   g_cand_i[NSPLIT * NROWS];
__device__ int   g_idx[NROWS];
__device__ float g_losspart[NROWS];

// ---- packed f32x2 helpers (Blackwell FFMA2) ----
__device__ __forceinline__ unsigned long long pack2(float x, float y) {
    unsigned long long u;
    asm("mov.b64 %0, {%1, %2};" : "=l"(u)
        : "r"(__float_as_uint(x)), "r"(__float_as_uint(y)));
    return u;
}
__device__ __forceinline__ unsigned long long dup2(float x) {
    unsigned long long u;
    unsigned int r = __float_as_uint(x);
    asm("mov.b64 %0, {%1, %1};" : "=l"(u) : "r"(r));
    return u;
}
__device__ __forceinline__ void fma2(float2& d, unsigned long long a, unsigned long long b) {
    unsigned long long* dp = reinterpret_cast<unsigned long long*>(&d);
    asm("fma.rn.f32x2 %0, %1, %2, %0;" : "+l"(*dp) : "l"(a), "l"(b));
}

// ---------------------------------------------------------------------------
// K1: transpose z (b,c,h,w) -> zflat[(b*1024 + h*32 + w)][c], coalesced both ways
// grid (8 c-chunks, 32 h, 8 b), block (32w, 32c)
// ---------------------------------------------------------------------------
__global__ void k_transpose(const float* __restrict__ z) {
    __shared__ float t[32][33];
    int b  = blockIdx.z;
    int h  = blockIdx.y;
    int c0 = blockIdx.x * 32;
    int tx = threadIdx.x, ty = threadIdx.y;
    // read: c = c0+ty, w = tx  (consecutive tx -> consecutive w: coalesced)
    t[ty][tx] = z[((size_t)(b * 256 + c0 + ty) * 32 + h) * 32 + tx];
    __syncthreads();
    // write: row n = b*1024 + h*32 + ty(=w), col c = c0+tx (coalesced)
    g_zflat[(size_t)(b * 1024 + h * 32 + ty) * DIM + c0 + tx] = t[tx][ty];
}

// ---------------------------------------------------------------------------
// K2: row norms for z and embedding. Sequential k-ascending order, separate
// mul/add roundings (no FMA contraction) to mirror the reference elementwise
// square + reduce.
// ---------------------------------------------------------------------------
__global__ void k_norms(const float* __restrict__ emb) {
    int i = blockIdx.x * blockDim.x + threadIdx.x;
    if (i < NROWS) {
        const float4* p = reinterpret_cast<const float4*>(g_zflat + (size_t)i * DIM);
        float s = 0.f;
        #pragma unroll 8
        for (int c = 0; c < DIM / 4; ++c) {
            float4 v = p[c];
            s = __fadd_rn(s, __fmul_rn(v.x, v.x));
            s = __fadd_rn(s, __fmul_rn(v.y, v.y));
            s = __fadd_rn(s, __fmul_rn(v.z, v.z));
            s = __fadd_rn(s, __fmul_rn(v.w, v.w));
        }
        g_znorm[i] = s;
    } else if (i < NROWS + NCODES) {
        int k = i - NROWS;
        const float4* p = reinterpret_cast<const float4*>(emb + (size_t)k * DIM);
        float s = 0.f;
        #pragma unroll 8
        for (int c = 0; c < DIM / 4; ++c) {
            float4 v = p[c];
            s = __fadd_rn(s, __fmul_rn(v.x, v.x));
            s = __fadd_rn(s, __fmul_rn(v.y, v.y));
            s = __fadd_rn(s, __fmul_rn(v.z, v.z));
            s = __fadd_rn(s, __fmul_rn(v.w, v.w));
        }
        g_enorm[k] = s;
    }
}

// ---------------------------------------------------------------------------
// K3: fused GEMM + argmin. grid (64 m-tiles, NSPLIT n-splits), 256 threads.
// Thread (tx=tid&15, ty=tid>>4) owns rows [ty*8, ty*8+8) x cols [tx*8, tx*8+8)
// of each 128x128 tile. K loop ascending; d = fl(fl(zn+en) - 2*dot);
// strict < keeps the first (lowest-index) minimum, matching jnp.argmin.
// ---------------------------------------------------------------------------
__global__ __launch_bounds__(256) void k_main(const float* __restrict__ emb) {
    __shared__ float As[KC][MT + 4];
    __shared__ float Bs[KC][NT + 4];

    const int tid = threadIdx.x;
    const int tx = tid & 15;
    const int ty = tid >> 4;
    const int m0 = blockIdx.x * MT;
    const int split = blockIdx.y;
    const int code_base = split * CODES_PER_SPLIT;

    float zn[8];
    #pragma unroll
    for (int r = 0; r < 8; ++r) zn[r] = g_znorm[m0 + ty * 8 + r];

    float bestd[8];
    int   besti[8];
    #pragma unroll
    for (int r = 0; r < 8; ++r) { bestd[r] = 3.4e38f; besti[r] = 0; }

    const int lk = tid & 31;   // k lane for loads (coalesced global reads)
    const int lm = tid >> 5;   // 0..7

    for (int n0 = 0; n0 < CODES_PER_SPLIT; n0 += NT) {
        float2 acc[8][4];
        #pragma unroll
        for (int r = 0; r < 8; ++r)
            #pragma unroll
            for (int j = 0; j < 4; ++j) acc[r][j] = make_float2(0.f, 0.f);

        for (int k0 = 0; k0 < DIM; k0 += KC) {
            __syncthreads();
            #pragma unroll
            for (int j = 0; j < 16; ++j) {
                int m = lm + j * 8;
                As[lk][m] = g_zflat[(size_t)(m0 + m) * DIM + k0 + lk];
            }
            #pragma unroll
            for (int j = 0; j < 16; ++j) {
                int n = lm + j * 8;
                Bs[lk][n] = emb[(size_t)(code_base + n0 + n) * DIM + k0 + lk];
            }
            __syncthreads();

            #pragma unroll
            for (int k = 0; k < KC; ++k) {
                float4 a0 = *reinterpret_cast<const float4*>(&As[k][ty * 8]);
                float4 a1 = *reinterpret_cast<const float4*>(&As[k][ty * 8 + 4]);
                float4 b0 = *reinterpret_cast<const float4*>(&Bs[k][tx * 8]);
                float4 b1 = *reinterpret_cast<const float4*>(&Bs[k][tx * 8 + 4]);
                unsigned long long bp0 = pack2(b0.x, b0.y);
                unsigned long long bp1 = pack2(b0.z, b0.w);
                unsigned long long bp2 = pack2(b1.x, b1.y);
                unsigned long long bp3 = pack2(b1.z, b1.w);
                float av[8] = {a0.x, a0.y, a0.z, a0.w, a1.x, a1.y, a1.z, a1.w};
                #pragma unroll
                for (int r = 0; r < 8; ++r) {
                    unsigned long long ap = dup2(av[r]);
                    fma2(acc[r][0], ap, bp0);
                    fma2(acc[r][1], ap, bp1);
                    fma2(acc[r][2], ap, bp2);
                    fma2(acc[r][3], ap, bp3);
                }
            }
        }

        // epilogue: d = (zn + en) - 2*dot, running argmin (ascending code order)
        #pragma unroll
        for (int j = 0; j < 8; ++j) {
            int code = code_base + n0 + tx * 8 + j;
            float en = __ldg(&g_enorm[code]);
            #pragma unroll
            for (int r = 0; r < 8; ++r) {
                float dot = (j & 1) ? acc[r][j >> 1].y : acc[r][j >> 1].x;
                float t = __fadd_rn(zn[r], en);
                float d = __fmaf_rn(-2.f, dot, t);   // == fl(t - fl(2*dot)), 2*dot exact
                if (d < bestd[r]) { bestd[r] = d; besti[r] = code; }
            }
        }
    }

    // reduce across the 16 tx lanes (consecutive tids -> 16-wide shuffle groups)
    #pragma unroll
    for (int r = 0; r < 8; ++r) {
        float bd = bestd[r];
        int   bi = besti[r];
        #pragma unroll
        for (int off = 8; off > 0; off >>= 1) {
            float od = __shfl_down_sync(0xffffffffu, bd, off, 16);
            int   oi = __shfl_down_sync(0xffffffffu, bi, off, 16);
            if (od < bd || (od == bd && oi < bi)) { bd = od; bi = oi; }
        }
        if (tx == 0) {
            int row = m0 + ty * 8 + r;
            g_cand_d[split * NROWS + row] = bd;
            g_cand_i[split * NROWS + row] = bi;
        }
    }
}

// ---------------------------------------------------------------------------
// K4: merge the NSPLIT candidates per row; write idx (as float) to out
// ---------------------------------------------------------------------------
__global__ void k_merge(float* __restrict__ out, int out_size) {
    int i = blockIdx.x * blockDim.x + threadIdx.x;
    if (i >= NROWS) return;
    float d0 = g_cand_d[i];
    int   i0 = g_cand_i[i];
    #pragma unroll
    for (int s = 1; s < NSPLIT; ++s) {
        float d1 = g_cand_d[s * NROWS + i];
        int   i1 = g_cand_i[s * NROWS + i];
        if (d1 < d0 || (d1 == d0 && i1 < i0)) { d0 = d1; i0 = i1; }
    }
    g_idx[i] = i0;
    if (out_size > OFF_IDX + i) out[OFF_IDX + i] = (float)i0;
}

// ---------------------------------------------------------------------------
// K5: gather z_q, straight-through output z + (z_q - z) (reference's exact
// rounding), transpose back to (b,c,h,w), per-row loss partial
// ---------------------------------------------------------------------------
__global__ void k_gather(const float* __restrict__ emb, float* __restrict__ out) {
    __shared__ float red[256];
    int n = blockIdx.x;
    int c = threadIdx.x;
    int b  = n >> 10;
    int hw = n & 1023;
    int code = g_idx[n];
    float zf = g_zflat[(size_t)n * DIM + c];
    float zq = emb[(size_t)code * DIM + c];
    float diff = __fsub_rn(zq, zf);                 // z_q - zc
    float st   = __fadd_rn(zf, diff);               // zc + sg(z_q - zc)
    out[(size_t)(b * 256 + c) * 1024 + hw] = st;
    red[c] = __fmul_rn(diff, diff);
    __syncthreads();
    #pragma unroll
    for (int s = 128; s > 0; s >>= 1) {
        if (c < s) red[c] = __fadd_rn(red[c], red[c + s]);
        __syncthreads();
    }
    if (c == 0) g_losspart[n] = red[0];
}

// K6: deterministic single-block loss reduction; loss = 1.25 * mean(diff^2)
__global__ void k_loss(float* __restrict__ out, int out_size) {
    __shared__ float red[256];
    int t = threadIdx.x;
    float s = 0.f;
    for (int i = t; i < NROWS; i += 256) s = __fadd_rn(s, g_losspart[i]);
    red[t] = s;
    __syncthreads();
    #pragma unroll
    for (int k = 128; k > 0; k >>= 1) {
        if (t < k) red[t] = __fadd_rn(red[t], red[t + k]);
        __syncthreads();
    }
    if (t == 0 && out_size > OFF_LOSS)
        out[OFF_LOSS] = 1.25f * red[0] / 2097152.0f;
}

// ---------------------------------------------------------------------------
extern "C" void kernel_launch(void* const* d_in, const int* in_sizes, int n_in,
                              void* d_out, int out_size) {
    const float* z   = (const float*)d_in[0];
    const float* emb = (const float*)d_in[1];
    // defensive: identify by size (z = 2,097,152; embedding = 4,194,304)
    if (n_in >= 2 && in_sizes[0] == NCODES * DIM && in_sizes[1] == NROWS * DIM) {
        const float* t = z; z = emb; emb = t;
    }
    float* out = (float*)d_out;

    k_transpose<<<dim3(8, 32, 8), dim3(32, 32)>>>(z);
    k_norms<<<(NROWS + NCODES + 255) / 256, 256>>>(emb);
    k_main<<<dim3(NROWS / MT, NSPLIT), 256>>>(emb);
    k_merge<<<NROWS / 256, 256>>>(out, out_size);
    k_gather<<<NROWS, 256>>>(emb, out);
    k_loss<<<1, 256>>>(out, out_size);
}

// round 4
// speedup vs baseline: 2.3710x; 2.3710x over previous
#include <cuda_runtime.h>
#include <cuda_bf16.h>
#include <cstdint>

// ---------------------------------------------------------------------------
// VectorQuantizer. Two device-code paths selected per compilation pass:
//  - sm_103a/"a"-feature pass: tcgen05 bf16 6-term split GEMM + fused argmin
//    (dot reproduced to ~1e-9 -> identical argmin to fp32 reference)
//  - baseline sm_103 pass: fp32 FFMA2 (packed f32x2) GEMM + fused argmin
//    (bit-identical numerics to the R1 kernel that passed at 1853us)
// Both bodies live in the SAME kernel with the same launch config and write
// the same scratch contract, so whichever SASS the runtime loads is correct.
// ---------------------------------------------------------------------------

#if defined(__CUDA_ARCH__) && (defined(__CUDA_ARCH_FEAT_SM103_ALL) || \
    defined(__CUDA_ARCH_FEAT_SM100_ALL) || defined(__CUDA_ARCH_FAMILY_SPECIFIC__))
#define HAS_TC 1
#else
#define HAS_TC 0
#endif

#define NROWS   8192
#define NCODES  16384
#define DIM     256
#define NZQ     2097152
#define OFF_LOSS NZQ
#define OFF_IDX  (NZQ + 1)

#define MT 256            // rows per CTA (2 subtiles of 128)
#define NT 256            // codes per CTA
#define N_MT (NROWS / MT)     // 32
#define N_NT (NCODES / NT)    // 64
#define KC 64             // k per tcgen05 stage (64 bf16 = 128B rows, SW128)
#define NTERMS 6
#define NSTAGES (NTERMS * (DIM / KC))   // 24

// ---- dynamic smem layout for tcgen05 path (bytes) ----
#define SM_A(buf, sub) ((buf) * 32768 + (sub) * 16384)   // 2x2x16KB
#define SM_B(buf)      (65536 + (buf) * 32768)           // 2x32KB
#define SM_CD          131072                            // float cand[256][2]
#define SM_CI          (SM_CD + 2048)                    // int   cand[256][2]
#define SM_TMEMPTR     (SM_CI + 2048)
#define SM_MBAR        (SM_TMEMPTR + 8)                  // 2 mbarriers
#define SMEM_DYN       (SM_MBAR + 64)

// idesc kind::f16: F32 acc(1<<4), A=BF16(1<<7), B=BF16(1<<10), N/8<<17, M/16<<24
#define IDESC 0x8400490u   // M=128, N=256

#define SWZ(o) ((o) ^ (((o) >> 3) & 0x70))

static __device__ __forceinline__ uint32_t smem_u32(const void* p) {
    return (uint32_t)__cvta_generic_to_shared(p);
}

// ---- device scratch ----
__device__ float g_zflat[NROWS * DIM];
__device__ float g_znorm[NROWS];
__device__ float g_enorm[NCODES];
__device__ __nv_bfloat16 g_zs0[NROWS * DIM];
__device__ __nv_bfloat16 g_zs1[NROWS * DIM];
__device__ __nv_bfloat16 g_zs2[NROWS * DIM];
__device__ __nv_bfloat16 g_es0[NCODES * DIM];
__device__ __nv_bfloat16 g_es1[NCODES * DIM];
__device__ __nv_bfloat16 g_es2[NCODES * DIM];
__device__ float g_cand_d[N_NT * NROWS];
__device__ int   g_cand_i[N_NT * NROWS];
__device__ int   g_idx[NROWS];
__device__ float g_losspart[NROWS];

// ---- packed f32x2 helpers (baseline sm_100+ feature; used by fallback) ----
__device__ __forceinline__ unsigned long long pack2(float x, float y) {
    unsigned long long u;
    asm("mov.b64 %0, {%1, %2};" : "=l"(u)
        : "r"(__float_as_uint(x)), "r"(__float_as_uint(y)));
    return u;
}
__device__ __forceinline__ unsigned long long dup2(float x) {
    unsigned long long u;
    unsigned int r = __float_as_uint(x);
    asm("mov.b64 %0, {%1, %1};" : "=l"(u) : "r"(r));
    return u;
}
__device__ __forceinline__ void fma2(float2& d, unsigned long long a, unsigned long long b) {
    unsigned long long* dp = reinterpret_cast<unsigned long long*>(&d);
    asm("fma.rn.f32x2 %0, %1, %2, %0;" : "+l"(*dp) : "l"(a), "l"(b));
}

#if HAS_TC
// ---- tcgen05 PTX wrappers (only compiled in the arch-"a" pass) ----
#define MBAR_INIT(a, c) \
    asm volatile("mbarrier.init.shared.b64 [%0], %1;" :: "r"(a), "r"(c) : "memory")

#define MBAR_WAIT(a, par) do {                                               \
    asm volatile(                                                            \
        "{\n\t.reg .pred P1;\n\t"                                            \
        "WAIT_LOOP_%=:\n\t"                                                  \
        "mbarrier.try_wait.parity.acquire.cta.shared::cta.b64 P1, [%0], %1, 0x989680;\n\t" \
        "@P1 bra.uni WAIT_DONE_%=;\n\t"                                      \
        "bra.uni WAIT_LOOP_%=;\n\t"                                          \
        "WAIT_DONE_%=:\n\t}"                                                 \
        :: "r"(a), "r"(par) : "memory");                                     \
} while (0)

#define TC_ALLOC(smem_addr, ncols) \
    asm volatile("tcgen05.alloc.cta_group::1.sync.aligned.shared::cta.b32 [%0], %1;" \
                 :: "r"(smem_addr), "r"(ncols) : "memory")
#define TC_DEALLOC(tmem, ncols) \
    asm volatile("tcgen05.dealloc.cta_group::1.sync.aligned.b32 %0, %1;" :: "r"(tmem), "r"(ncols))
#define TC_RELINQ() \
    asm volatile("tcgen05.relinquish_alloc_permit.cta_group::1.sync.aligned;")
#define TC_COMMIT(mbar) \
    asm volatile("tcgen05.commit.cta_group::1.mbarrier::arrive::one.shared::cluster.b64 [%0];" \
                 :: "r"(mbar) : "memory")
#define TC_FENCE_AFTER()  asm volatile("tcgen05.fence::after_thread_sync;" ::: "memory")
#define TC_FENCE_BEFORE() asm volatile("tcgen05.fence::before_thread_sync;" ::: "memory")
#define FENCE_ASYNC()     asm volatile("fence.proxy.async.shared::cta;" ::: "memory")
#define TC_WAIT_LD()      asm volatile("tcgen05.wait::ld.sync.aligned;" ::: "memory")

static __device__ __forceinline__ void mma_f16_ss(
    uint32_t d_tmem, uint64_t a_desc, uint64_t b_desc, uint32_t idesc, bool acc)
{
    uint32_t en = acc ? 1u : 0u;
    asm volatile(
        "{\n\t.reg .pred p;\n\t"
        "setp.ne.u32 p, %4, 0;\n\t"
        "tcgen05.mma.cta_group::1.kind::f16 [%0], %1, %2, %3, {%5, %5, %5, %5}, p;\n\t"
        "}"
        :: "r"(d_tmem), "l"(a_desc), "l"(b_desc), "r"(idesc), "r"(en), "r"(0u)
        : "memory");
}

#define DESC_BASE ((2ULL << 61) | (1ULL << 46) | (64ULL << 32) | (1ULL << 16))
static __device__ __forceinline__ uint64_t mk_desc(uint32_t addr) {
    return DESC_BASE | ((uint64_t)(addr >> 4) & 0x3FFF);
}

#define LDTM_X32(r, a)                                                        \
    asm volatile("tcgen05.ld.sync.aligned.32x32b.x32.b32 "                    \
        "{%0,%1,%2,%3,%4,%5,%6,%7,%8,%9,%10,%11,%12,%13,%14,%15,"             \
        "%16,%17,%18,%19,%20,%21,%22,%23,%24,%25,%26,%27,%28,%29,%30,%31}, [%32];" \
        : "=r"((r)[0]),"=r"((r)[1]),"=r"((r)[2]),"=r"((r)[3]),                \
          "=r"((r)[4]),"=r"((r)[5]),"=r"((r)[6]),"=r"((r)[7]),                \
          "=r"((r)[8]),"=r"((r)[9]),"=r"((r)[10]),"=r"((r)[11]),              \
          "=r"((r)[12]),"=r"((r)[13]),"=r"((r)[14]),"=r"((r)[15]),            \
          "=r"((r)[16]),"=r"((r)[17]),"=r"((r)[18]),"=r"((r)[19]),            \
          "=r"((r)[20]),"=r"((r)[21]),"=r"((r)[22]),"=r"((r)[23]),            \
          "=r"((r)[24]),"=r"((r)[25]),"=r"((r)[26]),"=r"((r)[27]),            \
          "=r"((r)[28]),"=r"((r)[29]),"=r"((r)[30]),"=r"((r)[31])             \
        : "r"(a))
#endif // HAS_TC

// ---------------------------------------------------------------------------
// K1: transpose z (b,c,h,w) -> zflat[row][c]
// ---------------------------------------------------------------------------
__global__ void k_transpose(const float* __restrict__ z) {
    __shared__ float t[32][33];
    int b = blockIdx.z, h = blockIdx.y, c0 = blockIdx.x * 32;
    int tx = threadIdx.x, ty = threadIdx.y;
    t[ty][tx] = z[((size_t)(b * 256 + c0 + ty) * 32 + h) * 32 + tx];
    __syncthreads();
    g_zflat[(size_t)(b * 1024 + h * 32 + ty) * DIM + c0 + tx] = t[tx][ty];
}

// ---------------------------------------------------------------------------
// K2: row norms (reference elementwise square + k-ascending sum rounding)
// ---------------------------------------------------------------------------
__global__ void k_norms(const float* __restrict__ emb) {
    int i = blockIdx.x * blockDim.x + threadIdx.x;
    if (i < NROWS) {
        const float4* p = reinterpret_cast<const float4*>(g_zflat + (size_t)i * DIM);
        float s = 0.f;
        #pragma unroll 8
        for (int c = 0; c < DIM / 4; ++c) {
            float4 v = p[c];
            s = __fadd_rn(s, __fmul_rn(v.x, v.x));
            s = __fadd_rn(s, __fmul_rn(v.y, v.y));
            s = __fadd_rn(s, __fmul_rn(v.z, v.z));
            s = __fadd_rn(s, __fmul_rn(v.w, v.w));
        }
        g_znorm[i] = s;
    } else if (i < NROWS + NCODES) {
        int k = i - NROWS;
        const float4* p = reinterpret_cast<const float4*>(emb + (size_t)k * DIM);
        float s = 0.f;
        #pragma unroll 8
        for (int c = 0; c < DIM / 4; ++c) {
            float4 v = p[c];
            s = __fadd_rn(s, __fmul_rn(v.x, v.x));
            s = __fadd_rn(s, __fmul_rn(v.y, v.y));
            s = __fadd_rn(s, __fmul_rn(v.z, v.z));
            s = __fadd_rn(s, __fmul_rn(v.w, v.w));
        }
        g_enorm[k] = s;
    }
}

// ---------------------------------------------------------------------------
// K3a/b: bf16 3-way splits (exact decomposition of fp32 to ~2^-24)
// ---------------------------------------------------------------------------
__global__ void k_split_z() {
    int i = blockIdx.x * blockDim.x + threadIdx.x;
    if (i >= NROWS * DIM) return;
    float x = g_zflat[i];
    __nv_bfloat16 h1 = __float2bfloat16(x);
    float r1 = __fsub_rn(x, __bfloat162float(h1));
    __nv_bfloat16 h2 = __float2bfloat16(r1);
    float r2 = __fsub_rn(r1, __bfloat162float(h2));
    __nv_bfloat16 h3 = __float2bfloat16(r2);
    g_zs0[i] = h1; g_zs1[i] = h2; g_zs2[i] = h3;
}
__global__ void k_split_e(const float* __restrict__ emb) {
    int i = blockIdx.x * blockDim.x + threadIdx.x;
    if (i >= NCODES * DIM) return;
    float x = emb[i];
    __nv_bfloat16 h1 = __float2bfloat16(x);
    float r1 = __fsub_rn(x, __bfloat162float(h1));
    __nv_bfloat16 h2 = __float2bfloat16(r1);
    float r2 = __fsub_rn(r1, __bfloat162float(h2));
    __nv_bfloat16 h3 = __float2bfloat16(r2);
    g_es0[i] = h1; g_es1[i] = h2; g_es2[i] = h3;
}

// ---------------------------------------------------------------------------
// K4: GEMM + fused argmin. grid = N_MT*N_NT (bid%32 -> m_tile, bid/32 ->
// n_tile), 512 threads, SMEM_DYN dynamic smem. Tile 256(M) x 256(N).
//   HAS_TC:  tcgen05 bf16 6-term split, 24 double-buffered K-stages.
//   else:    fp32 FFMA2, two 256x128 n-halves, 8x8 per thread (R1 numerics).
// Contract: writes g_cand_d/g_cand_i[n_tile*NROWS + row] (first-index ties).
// ---------------------------------------------------------------------------
__global__ __launch_bounds__(512, 1) void k_mma(const float* __restrict__ emb) {
    extern __shared__ char smem[];
    const int tid = threadIdx.x;
    const int m_tile = blockIdx.x & (N_MT - 1);
    const int n_tile = blockIdx.x / N_MT;
    const int m0 = m_tile * MT;
    const int n0 = n_tile * NT;

#if HAS_TC
    const uint32_t sbase = smem_u32(smem);
    const int wid = tid >> 5;
    const int lane = tid & 31;

    if (wid == 0) TC_ALLOC(sbase + SM_TMEMPTR, 512);
    if (tid == 0) {
        MBAR_INIT(sbase + SM_MBAR, 1);
        MBAR_INIT(sbase + SM_MBAR + 8, 1);
    }
    __syncthreads();
    uint32_t tmem;
    asm volatile("ld.shared.b32 %0, [%1];" : "=r"(tmem) : "r"(sbase + SM_TMEMPTR));

    const __nv_bfloat16* zsrc[3] = {g_zs0, g_zs1, g_zs2};
    const __nv_bfloat16* esrc[3] = {g_es0, g_es1, g_es2};
    const int za[NTERMS] = {0, 0, 1, 1, 0, 2};
    const int eb[NTERMS] = {0, 1, 0, 1, 2, 0};

    int ph0 = 0, ph1 = 0;

    for (int s = 0; s < NSTAGES; ++s) {
        const int buf = s & 1;
        const int t = s >> 2;
        const int kc = (s & 3) * KC;

        if (s >= 2) {       // wait until MMAs on this buffer (stage s-2) finished
            if (buf == 0) { MBAR_WAIT(sbase + SM_MBAR, ph0); ph0 ^= 1; }
            else          { MBAR_WAIT(sbase + SM_MBAR + 8, ph1); ph1 ^= 1; }
        }

        const __nv_bfloat16* zp = zsrc[za[t]];
        #pragma unroll
        for (int i = 0; i < 4; ++i) {
            int ch = tid + i * 512;
            int sub = ch >> 10, r = (ch >> 3) & 127, k8 = ch & 7;
            uint4 v = *reinterpret_cast<const uint4*>(
                zp + (size_t)(m0 + sub * 128 + r) * DIM + kc + k8 * 8);
            *reinterpret_cast<uint4*>(smem + SM_A(buf, sub) + SWZ(r * 128 + k8 * 16)) = v;
        }
        const __nv_bfloat16* ep = esrc[eb[t]];
        #pragma unroll
        for (int i = 0; i < 4; ++i) {
            int ch = tid + i * 512;
            int r = ch >> 3, k8 = ch & 7;
            uint4 v = *reinterpret_cast<const uint4*>(
                ep + (size_t)(n0 + r) * DIM + kc + k8 * 8);
            *reinterpret_cast<uint4*>(smem + SM_B(buf) + SWZ(r * 128 + k8 * 16)) = v;
        }
        __syncthreads();

        if (tid == 0) {
            FENCE_ASYNC();
            uint64_t bd = mk_desc(sbase + SM_B(buf));
            #pragma unroll
            for (int sub = 0; sub < 2; ++sub) {
                uint64_t ad = mk_desc(sbase + SM_A(buf, sub));
                #pragma unroll
                for (int k = 0; k < 4; ++k)
                    mma_f16_ss(tmem + sub * 256, ad + k * 2, bd + k * 2,
                               IDESC, (s > 0) || (k > 0));
            }
            TC_COMMIT(sbase + SM_MBAR + buf * 8);
        }
    }

    MBAR_WAIT(sbase + SM_MBAR, ph0);
    MBAR_WAIT(sbase + SM_MBAR + 8, ph1);
    TC_FENCE_AFTER();

    // epilogue: d = (zn+en) - 2*dot, argmin over this tile's 256 codes
    const int sub  = (wid >> 2) & 1;
    const int half = wid >> 3;
    const int rl   = (wid & 3) * 32 + lane;
    const int grow = m0 + sub * 128 + rl;
    const float zn = g_znorm[grow];

    float bd = 3.4e38f;
    int   bi = 0;
    #pragma unroll
    for (int j = 0; j < 4; ++j) {
        uint32_t regs[32];
        LDTM_X32(regs, tmem + sub * 256 + half * 128 + j * 32);
        TC_WAIT_LD();
        #pragma unroll
        for (int c = 0; c < 32; ++c) {
            int code = n0 + half * 128 + j * 32 + c;
            float dot = __uint_as_float(regs[c]);
            float d = __fmaf_rn(-2.f, dot, __fadd_rn(zn, __ldg(&g_enorm[code])));
            if (d < bd) { bd = d; bi = code; }
        }
    }
    TC_FENCE_BEFORE();

    float* cd = reinterpret_cast<float*>(smem + SM_CD);
    int*   ci = reinterpret_cast<int*>(smem + SM_CI);
    cd[(sub * 128 + rl) * 2 + half] = bd;
    ci[(sub * 128 + rl) * 2 + half] = bi;
    __syncthreads();

    if (tid < 256) {
        float d0 = cd[tid * 2], d1 = cd[tid * 2 + 1];
        int   i0 = ci[tid * 2], i1 = ci[tid * 2 + 1];
        if (d1 < d0) { d0 = d1; i0 = i1; }    // half0 first => first-index ties
        g_cand_d[n_tile * NROWS + m0 + tid] = d0;
        g_cand_i[n_tile * NROWS + m0 + tid] = i0;
    }
    __syncthreads();
    if (wid == 0) {
        TC_RELINQ();
        TC_DEALLOC(tmem, 512);
    }

#else  // ---------------- fallback: fp32 FFMA2 GEMM-argmin ------------------
    float (*As)[260] = reinterpret_cast<float(*)[260]>(smem);          // 32x260
    float (*Bs)[132] = reinterpret_cast<float(*)[132]>(smem + 33280);  // 32x132

    const int tx = tid & 15;     // 16 col-groups of 8 (covers 128 cols)
    const int ty = tid >> 4;     // 32 row-groups of 8 (covers 256 rows)
    const int lk = tid & 31;
    const int lm = tid >> 5;     // 0..15

    float zn8[8];
    #pragma unroll
    for (int r = 0; r < 8; ++r) zn8[r] = g_znorm[m0 + ty * 8 + r];

    float bestd[8];
    int   besti[8];
    #pragma unroll
    for (int r = 0; r < 8; ++r) { bestd[r] = 3.4e38f; besti[r] = 0; }

    for (int hf = 0; hf < 2; ++hf) {
        const int nb = n0 + hf * 128;
        float2 acc[8][4];
        #pragma unroll
        for (int r = 0; r < 8; ++r)
            #pragma unroll
            for (int j = 0; j < 4; ++j) acc[r][j] = make_float2(0.f, 0.f);

        for (int k0 = 0; k0 < DIM; k0 += 32) {
            __syncthreads();
            #pragma unroll
            for (int j = 0; j < 16; ++j) {
                int row = lm + j * 16;
                As[lk][row] = g_zflat[(size_t)(m0 + row) * DIM + k0 + lk];
            }
            #pragma unroll
            for (int j = 0; j < 8; ++j) {
                int row = lm + j * 16;
                Bs[lk][row] = emb[(size_t)(nb + row) * DIM + k0 + lk];
            }
            __syncthreads();

            #pragma unroll
            for (int k = 0; k < 32; ++k) {
                float4 a0 = *reinterpret_cast<const float4*>(&As[k][ty * 8]);
                float4 a1 = *reinterpret_cast<const float4*>(&As[k][ty * 8 + 4]);
                float4 b0 = *reinterpret_cast<const float4*>(&Bs[k][tx * 8]);
                float4 b1 = *reinterpret_cast<const float4*>(&Bs[k][tx * 8 + 4]);
                unsigned long long bp0 = pack2(b0.x, b0.y);
                unsigned long long bp1 = pack2(b0.z, b0.w);
                unsigned long long bp2 = pack2(b1.x, b1.y);
                unsigned long long bp3 = pack2(b1.z, b1.w);
                float av[8] = {a0.x, a0.y, a0.z, a0.w, a1.x, a1.y, a1.z, a1.w};
                #pragma unroll
                for (int r = 0; r < 8; ++r) {
                    unsigned long long ap = dup2(av[r]);
                    fma2(acc[r][0], ap, bp0);
                    fma2(acc[r][1], ap, bp1);
                    fma2(acc[r][2], ap, bp2);
                    fma2(acc[r][3], ap, bp3);
                }
            }
        }

        #pragma unroll
        for (int j = 0; j < 8; ++j) {
            int code = nb + tx * 8 + j;
            float en = __ldg(&g_enorm[code]);
            #pragma unroll
            for (int r = 0; r < 8; ++r) {
                float dot = (j & 1) ? acc[r][j >> 1].y : acc[r][j >> 1].x;
                float d = __fmaf_rn(-2.f, dot, __fadd_rn(zn8[r], en));
                if (d < bestd[r]) { bestd[r] = d; besti[r] = code; }
            }
        }
    }

    // reduce across the 16 tx lanes (16-wide shuffle groups)
    #pragma unroll
    for (int r = 0; r < 8; ++r) {
        float bd = bestd[r];
        int   bi = besti[r];
        #pragma unroll
        for (int off = 8; off > 0; off >>= 1) {
            float od = __shfl_down_sync(0xffffffffu, bd, off, 16);
            int   oi = __shfl_down_sync(0xffffffffu, bi, off, 16);
            if (od < bd || (od == bd && oi < bi)) { bd = od; bi = oi; }
        }
        if (tx == 0) {
            int row = m0 + ty * 8 + r;
            g_cand_d[n_tile * NROWS + row] = bd;
            g_cand_i[n_tile * NROWS + row] = bi;
        }
    }
#endif
}

// ---------------------------------------------------------------------------
// K5: merge 64 n-chunks per row (ascending => first-index tie-break)
// ---------------------------------------------------------------------------
__global__ void k_merge(float* __restrict__ out, int out_size) {
    int i = blockIdx.x * blockDim.x + threadIdx.x;
    if (i >= NROWS) return;
    float d0 = g_cand_d[i];
    int   i0 = g_cand_i[i];
    for (int s = 1; s < N_NT; ++s) {
        float d1 = g_cand_d[s * NROWS + i];
        int   i1 = g_cand_i[s * NROWS + i];
        if (d1 < d0) { d0 = d1; i0 = i1; }
    }
    g_idx[i] = i0;
    if (out_size > OFF_IDX + i) out[OFF_IDX + i] = (float)i0;
}

// ---------------------------------------------------------------------------
// K6: gather + straight-through + transpose back + loss partials
// ---------------------------------------------------------------------------
__global__ void k_gather(const float* __restrict__ emb, float* __restrict__ out) {
    __shared__ float red[256];
    int n = blockIdx.x, c = threadIdx.x;
    int b = n >> 10, hw = n & 1023;
    int code = g_idx[n];
    float zf = g_zflat[(size_t)n * DIM + c];
    float zq = emb[(size_t)code * DIM + c];
    float diff = __fsub_rn(zq, zf);
    float st = __fadd_rn(zf, diff);
    out[(size_t)(b * 256 + c) * 1024 + hw] = st;
    red[c] = __fmul_rn(diff, diff);
    __syncthreads();
    #pragma unroll
    for (int s = 128; s > 0; s >>= 1) {
        if (c < s) red[c] = __fadd_rn(red[c], red[c + s]);
        __syncthreads();
    }
    if (c == 0) g_losspart[n] = red[0];
}

__global__ void k_loss(float* __restrict__ out, int out_size) {
    __shared__ float red[256];
    int t = threadIdx.x;
    float s = 0.f;
    for (int i = t; i < NROWS; i += 256) s = __fadd_rn(s, g_losspart[i]);
    red[t] = s;
    __syncthreads();
    #pragma unroll
    for (int k = 128; k > 0; k >>= 1) {
        if (t < k) red[t] = __fadd_rn(red[t], red[t + k]);
        __syncthreads();
    }
    if (t == 0 && out_size > OFF_LOSS)
        out[OFF_LOSS] = 1.25f * red[0] / 2097152.0f;
}

// ---------------------------------------------------------------------------
extern "C" void kernel_launch(void* const* d_in, const int* in_sizes, int n_in,
                              void* d_out, int out_size) {
    const float* z   = (const float*)d_in[0];
    const float* emb = (const float*)d_in[1];
    if (n_in >= 2 && in_sizes[0] == NCODES * DIM && in_sizes[1] == NROWS * DIM) {
        const float* t = z; z = emb; emb = t;
    }
    float* out = (float*)d_out;

    cudaFuncSetAttribute(k_mma, cudaFuncAttributeMaxDynamicSharedMemorySize, SMEM_DYN);

    k_transpose<<<dim3(8, 32, 8), dim3(32, 32)>>>(z);
    k_norms<<<(NROWS + NCODES + 255) / 256, 256>>>(emb);
    k_split_z<<<(NROWS * DIM + 255) / 256, 256>>>();
    k_split_e<<<(NCODES * DIM + 255) / 256, 256>>>(emb);
    k_mma<<<N_MT * N_NT, 512, SMEM_DYN>>>(emb);
    k_merge<<<NROWS / 256, 256>>>(out, out_size);
    k_gather<<<NROWS, 256>>>(emb, out);
    k_loss<<<1, 256>>>(out, out_size);
}

// round 5
// speedup vs baseline: 2.9288x; 1.2353x over previous
#include <cuda_runtime.h>
#include <cuda_bf16.h>
#include <cstdint>

// ---------------------------------------------------------------------------
// VectorQuantizer. tcgen05 bf16 6-term split GEMM + fused argmin (sm_103a
// pass), fp32 FFMA2 fallback (baseline sm_103 pass). Persistent CTAs, split
// operands cached in smem slots: 6 loads per K-chunk instead of 12.
// ---------------------------------------------------------------------------

#if defined(__CUDA_ARCH__) && (defined(__CUDA_ARCH_FEAT_SM103_ALL) || \
    defined(__CUDA_ARCH_FEAT_SM100_ALL) || defined(__CUDA_ARCH_FAMILY_SPECIFIC__))
#define HAS_TC 1
#else
#define HAS_TC 0
#endif

#define NROWS   8192
#define NCODES  16384
#define DIM     256
#define NZQ     2097152
#define OFF_LOSS NZQ
#define OFF_IDX  (NZQ + 1)

#define MT 256
#define NT 256
#define N_MT (NROWS / MT)     // 32
#define N_NT (NCODES / NT)    // 64
#define NTILES (N_MT * N_NT)  // 2048
#define GRID_MMA 148
#define KC 64                 // k per stage
#define NKC (DIM / KC)        // 4
#define STAGES_PER_TILE 24    // 4 kc x 6 terms

// ---- dynamic smem layout (bytes): A slots 2x32KB, B slots 3x32KB ----
#define SM_A(s)   ((s) * 32768)
#define SM_B(s)   (65536 + (s) * 32768)
#define SM_CD     163840
#define SM_CI     (SM_CD + 2048)
#define SM_TMEMPTR (SM_CI + 2048)
#define SM_MBAR   (SM_TMEMPTR + 8)
#define SMEM_DYN  (SM_MBAR + 64)

// idesc kind::f16: F32 acc(1<<4), A=BF16(1<<7), B=BF16(1<<10), N/8<<17, M/16<<24
#define IDESC 0x8400490u   // M=128, N=256

#define SWZ(o) ((o) ^ (((o) >> 3) & 0x70))

static __device__ __forceinline__ uint32_t smem_u32(const void* p) {
    return (uint32_t)__cvta_generic_to_shared(p);
}

// ---- device scratch ----
__device__ float g_zflat[NROWS * DIM];
__device__ float g_znorm[NROWS];
__device__ float g_enorm[NCODES];
__device__ __nv_bfloat16 g_zs0[NROWS * DIM];
__device__ __nv_bfloat16 g_zs1[NROWS * DIM];
__device__ __nv_bfloat16 g_zs2[NROWS * DIM];
__device__ __nv_bfloat16 g_es0[NCODES * DIM];
__device__ __nv_bfloat16 g_es1[NCODES * DIM];
__device__ __nv_bfloat16 g_es2[NCODES * DIM];
__device__ float g_cand_d[N_NT * NROWS];
__device__ int   g_cand_i[N_NT * NROWS];
__device__ int   g_idx[NROWS];
__device__ float g_losspart[NROWS];

// ---- packed f32x2 helpers (fallback path) ----
__device__ __forceinline__ unsigned long long pack2(float x, float y) {
    unsigned long long u;
    asm("mov.b64 %0, {%1, %2};" : "=l"(u)
        : "r"(__float_as_uint(x)), "r"(__float_as_uint(y)));
    return u;
}
__device__ __forceinline__ unsigned long long dup2(float x) {
    unsigned long long u;
    unsigned int r = __float_as_uint(x);
    asm("mov.b64 %0, {%1, %1};" : "=l"(u) : "r"(r));
    return u;
}
__device__ __forceinline__ void fma2(float2& d, unsigned long long a, unsigned long long b) {
    unsigned long long* dp = reinterpret_cast<unsigned long long*>(&d);
    asm("fma.rn.f32x2 %0, %1, %2, %0;" : "+l"(*dp) : "l"(a), "l"(b));
}

#if HAS_TC
#define MBAR_INIT(a, c) \
    asm volatile("mbarrier.init.shared.b64 [%0], %1;" :: "r"(a), "r"(c) : "memory")

#define MBAR_WAIT(a, par) do {                                               \
    asm volatile(                                                            \
        "{\n\t.reg .pred P1;\n\t"                                            \
        "WAIT_LOOP_%=:\n\t"                                                  \
        "mbarrier.try_wait.parity.acquire.cta.shared::cta.b64 P1, [%0], %1, 0x989680;\n\t" \
        "@P1 bra.uni WAIT_DONE_%=;\n\t"                                      \
        "bra.uni WAIT_LOOP_%=;\n\t"                                          \
        "WAIT_DONE_%=:\n\t}"                                                 \
        :: "r"(a), "r"(par) : "memory");                                     \
} while (0)

#define TC_ALLOC(smem_addr, ncols) \
    asm volatile("tcgen05.alloc.cta_group::1.sync.aligned.shared::cta.b32 [%0], %1;" \
                 :: "r"(smem_addr), "r"(ncols) : "memory")
#define TC_DEALLOC(tmem, ncols) \
    asm volatile("tcgen05.dealloc.cta_group::1.sync.aligned.b32 %0, %1;" :: "r"(tmem), "r"(ncols))
#define TC_RELINQ() \
    asm volatile("tcgen05.relinquish_alloc_permit.cta_group::1.sync.aligned;")
#define TC_COMMIT(mbar) \
    asm volatile("tcgen05.commit.cta_group::1.mbarrier::arrive::one.shared::cluster.b64 [%0];" \
                 :: "r"(mbar) : "memory")
#define TC_FENCE_AFTER()  asm volatile("tcgen05.fence::after_thread_sync;" ::: "memory")
#define TC_FENCE_BEFORE() asm volatile("tcgen05.fence::before_thread_sync;" ::: "memory")
#define FENCE_ASYNC()     asm volatile("fence.proxy.async.shared::cta;" ::: "memory")
#define TC_WAIT_LD()      asm volatile("tcgen05.wait::ld.sync.aligned;" ::: "memory")

static __device__ __forceinline__ void mma_f16_ss(
    uint32_t d_tmem, uint64_t a_desc, uint64_t b_desc, uint32_t idesc, bool acc)
{
    uint32_t en = acc ? 1u : 0u;
    asm volatile(
        "{\n\t.reg .pred p;\n\t"
        "setp.ne.u32 p, %4, 0;\n\t"
        "tcgen05.mma.cta_group::1.kind::f16 [%0], %1, %2, %3, {%5, %5, %5, %5}, p;\n\t"
        "}"
        :: "r"(d_tmem), "l"(a_desc), "l"(b_desc), "r"(idesc), "r"(en), "r"(0u)
        : "memory");
}

#define DESC_BASE ((2ULL << 61) | (1ULL << 46) | (64ULL << 32) | (1ULL << 16))
static __device__ __forceinline__ uint64_t mk_desc(uint32_t addr) {
    return DESC_BASE | ((uint64_t)(addr >> 4) & 0x3FFF);
}

#define LDTM_X32(r, a)                                                        \
    asm volatile("tcgen05.ld.sync.aligned.32x32b.x32.b32 "                    \
        "{%0,%1,%2,%3,%4,%5,%6,%7,%8,%9,%10,%11,%12,%13,%14,%15,"             \
        "%16,%17,%18,%19,%20,%21,%22,%23,%24,%25,%26,%27,%28,%29,%30,%31}, [%32];" \
        : "=r"((r)[0]),"=r"((r)[1]),"=r"((r)[2]),"=r"((r)[3]),                \
          "=r"((r)[4]),"=r"((r)[5]),"=r"((r)[6]),"=r"((r)[7]),                \
          "=r"((r)[8]),"=r"((r)[9]),"=r"((r)[10]),"=r"((r)[11]),              \
          "=r"((r)[12]),"=r"((r)[13]),"=r"((r)[14]),"=r"((r)[15]),            \
          "=r"((r)[16]),"=r"((r)[17]),"=r"((r)[18]),"=r"((r)[19]),            \
          "=r"((r)[20]),"=r"((r)[21]),"=r"((r)[22]),"=r"((r)[23]),            \
          "=r"((r)[24]),"=r"((r)[25]),"=r"((r)[26]),"=r"((r)[27]),            \
          "=r"((r)[28]),"=r"((r)[29]),"=r"((r)[30]),"=r"((r)[31])             \
        : "r"(a))
#endif // HAS_TC

// ---------------------------------------------------------------------------
// K0: transpose z (b,c,h,w) -> zflat[row][c], fused elementwise bf16 3-split
// ---------------------------------------------------------------------------
__global__ void k_transpose(const float* __restrict__ z) {
    __shared__ float t[32][33];
    int b = blockIdx.z, h = blockIdx.y, c0 = blockIdx.x * 32;
    int tx = threadIdx.x, ty = threadIdx.y;
    t[ty][tx] = z[((size_t)(b * 256 + c0 + ty) * 32 + h) * 32 + tx];
    __syncthreads();
    size_t o = (size_t)(b * 1024 + h * 32 + ty) * DIM + c0 + tx;
    float x = t[tx][ty];
    g_zflat[o] = x;
    __nv_bfloat16 h1 = __float2bfloat16(x);
    float r1 = __fsub_rn(x, __bfloat162float(h1));
    __nv_bfloat16 h2 = __float2bfloat16(r1);
    float r2 = __fsub_rn(r1, __bfloat162float(h2));
    g_zs0[o] = h1; g_zs1[o] = h2; g_zs2[o] = __float2bfloat16(r2);
}

// ---------------------------------------------------------------------------
// K1: row norms (reference elementwise square + k-ascending sum rounding)
// ---------------------------------------------------------------------------
__global__ void k_norms(const float* __restrict__ emb) {
    int i = blockIdx.x * blockDim.x + threadIdx.x;
    if (i < NROWS) {
        const float4* p = reinterpret_cast<const float4*>(g_zflat + (size_t)i * DIM);
        float s = 0.f;
        #pragma unroll 8
        for (int c = 0; c < DIM / 4; ++c) {
            float4 v = p[c];
            s = __fadd_rn(s, __fmul_rn(v.x, v.x));
            s = __fadd_rn(s, __fmul_rn(v.y, v.y));
            s = __fadd_rn(s, __fmul_rn(v.z, v.z));
            s = __fadd_rn(s, __fmul_rn(v.w, v.w));
        }
        g_znorm[i] = s;
    } else if (i < NROWS + NCODES) {
        int k = i - NROWS;
        const float4* p = reinterpret_cast<const float4*>(emb + (size_t)k * DIM);
        float s = 0.f;
        #pragma unroll 8
        for (int c = 0; c < DIM / 4; ++c) {
            float4 v = p[c];
            s = __fadd_rn(s, __fmul_rn(v.x, v.x));
            s = __fadd_rn(s, __fmul_rn(v.y, v.y));
            s = __fadd_rn(s, __fmul_rn(v.z, v.z));
            s = __fadd_rn(s, __fmul_rn(v.w, v.w));
        }
        g_enorm[k] = s;
    }
}

// ---------------------------------------------------------------------------
// K2: embedding bf16 3-way split (elementwise, coalesced)
// ---------------------------------------------------------------------------
__global__ void k_split_e(const float* __restrict__ emb) {
    int i = blockIdx.x * blockDim.x + threadIdx.x;
    if (i >= NCODES * DIM) return;
    float x = emb[i];
    __nv_bfloat16 h1 = __float2bfloat16(x);
    float r1 = __fsub_rn(x, __bfloat162float(h1));
    __nv_bfloat16 h2 = __float2bfloat16(r1);
    float r2 = __fsub_rn(r1, __bfloat162float(h2));
    g_es0[i] = h1; g_es1[i] = h2; g_es2[i] = __float2bfloat16(r2);
}

// ---------------------------------------------------------------------------
// K3: persistent GEMM + fused argmin. grid=148, 512 threads.
// Per tile (256M x 256N): 4 kc-chunks x 6 term-stages. Per kc each of
// z1,z2,z3 / e1,e2,e3 is loaded into its smem slot exactly once:
//   j:      0        1        2        3        4        5
//   term:  z1*e2    z1*e3    z1*e1    z2*e2    z2*e1    z3*e1
//   a_slot: X        X        X        Y        Y        X     (X/Y alt per kc)
//   b_slot: 0        1        2        0        2        2
//   a_load: z1       -        -        z2       -        z3
//   b_load: e2       e3       e1       -        -        -
// All overwrite hazards have distance >= 2 stages -> covered by waiting for
// stage (gs-2)'s MMA commit (mbar[gs&1], parity (gs/2)&1, gs global).
// ---------------------------------------------------------------------------
__global__ __launch_bounds__(512, 1) void k_mma(const float* __restrict__ emb) {
    extern __shared__ char smem[];
    const int tid = threadIdx.x;

#if HAS_TC
    const uint32_t sbase = smem_u32(smem);
    const int wid = tid >> 5;
    const int lane = tid & 31;

    if (wid == 0) TC_ALLOC(sbase + SM_TMEMPTR, 512);
    if (tid == 0) {
        MBAR_INIT(sbase + SM_MBAR, 1);
        MBAR_INIT(sbase + SM_MBAR + 8, 1);
    }
    __syncthreads();
    uint32_t tmem;
    asm volatile("ld.shared.b32 %0, [%1];" : "=r"(tmem) : "r"(sbase + SM_TMEMPTR));

    const __nv_bfloat16* zsrc[3] = {g_zs0, g_zs1, g_zs2};
    const __nv_bfloat16* esrc[3] = {g_es0, g_es1, g_es2};
    // per-j tables
    const int tab_as[6]  = {0, 0, 0, 1, 1, 0};   // a slot (xor'd with kc&1)
    const int tab_bs[6]  = {0, 1, 2, 0, 2, 2};   // b slot
    const int tab_al[6]  = {0, -1, -1, 1, -1, 2};  // a split to load (-1 none)
    const int tab_bl[6]  = {1, 2, 0, -1, -1, -1};  // b split to load (-1 none)

    float* cd = reinterpret_cast<float*>(smem + SM_CD);
    int*   ci = reinterpret_cast<int*>(smem + SM_CI);

    // epilogue geometry (fixed per thread)
    const int sub  = (wid >> 2) & 1;
    const int half = wid >> 3;
    const int rl   = (wid & 3) * 32 + lane;

    long long gs = 0;   // global stage counter across tiles

    for (int tile = blockIdx.x; tile < NTILES; tile += GRID_MMA) {
        const int m0 = (tile & (N_MT - 1)) * MT;
        const int n_tile = tile / N_MT;
        const int n0 = n_tile * NT;

        for (int s = 0; s < STAGES_PER_TILE; ++s, ++gs) {
            const int kc = s / 6;
            const int j  = s - kc * 6;
            const int kb = kc * KC;
            const int a_slot = tab_as[j] ^ (kc & 1);
            const int b_slot = tab_bs[j];

            if (gs >= 2) {   // wait for stage gs-2's MMAs (buffer reuse safety)
                long long w = gs - 2;
                MBAR_WAIT(sbase + SM_MBAR + ((int)(w & 1)) * 8, (int)((w >> 1) & 1));
            }

            if (tab_al[j] >= 0) {
                const __nv_bfloat16* zp = zsrc[tab_al[j]];
                #pragma unroll
                for (int i = 0; i < 4; ++i) {
                    int ch = tid + i * 512;
                    int sb2 = ch >> 10, r = (ch >> 3) & 127, k8 = ch & 7;
                    uint4 v = *reinterpret_cast<const uint4*>(
                        zp + (size_t)(m0 + sb2 * 128 + r) * DIM + kb + k8 * 8);
                    *reinterpret_cast<uint4*>(
                        smem + SM_A(a_slot) + sb2 * 16384 + SWZ(r * 128 + k8 * 16)) = v;
                }
            }
            if (tab_bl[j] >= 0) {
                const __nv_bfloat16* ep = esrc[tab_bl[j]];
                #pragma unroll
                for (int i = 0; i < 4; ++i) {
                    int ch = tid + i * 512;
                    int r = ch >> 3, k8 = ch & 7;
                    uint4 v = *reinterpret_cast<const uint4*>(
                        ep + (size_t)(n0 + r) * DIM + kb + k8 * 8);
                    *reinterpret_cast<uint4*>(
                        smem + SM_B(b_slot) + SWZ(r * 128 + k8 * 16)) = v;
                }
            }
            __syncthreads();

            if (tid == 0) {
                if (s == 0) TC_FENCE_AFTER();   // order vs prev tile's LDTM reads
                FENCE_ASYNC();
                uint64_t bd = mk_desc(sbase + SM_B(b_slot));
                #pragma unroll
                for (int sb2 = 0; sb2 < 2; ++sb2) {
                    uint64_t ad = mk_desc(sbase + SM_A(a_slot) + sb2 * 16384);
                    #pragma unroll
                    for (int k = 0; k < 4; ++k)
                        mma_f16_ss(tmem + sb2 * 256, ad + k * 2, bd + k * 2,
                                   IDESC, (s > 0) || (k > 0));
                }
                TC_COMMIT(sbase + SM_MBAR + ((int)(gs & 1)) * 8);
            }
        }

        // drain last two stages (gs-2, gs-1)
        {
            long long w = gs - 2;
            MBAR_WAIT(sbase + SM_MBAR + ((int)(w & 1)) * 8, (int)((w >> 1) & 1));
            w = gs - 1;
            MBAR_WAIT(sbase + SM_MBAR + ((int)(w & 1)) * 8, (int)((w >> 1) & 1));
        }
        TC_FENCE_AFTER();

        // epilogue: d = (zn+en) - 2*dot, argmin over this tile's 256 codes
        const float zn = g_znorm[m0 + sub * 128 + rl];
        float bd2 = 3.4e38f;
        int   bi2 = 0;
        #pragma unroll
        for (int jj = 0; jj < 4; ++jj) {
            uint32_t regs[32];
            LDTM_X32(regs, tmem + sub * 256 + half * 128 + jj * 32);
            TC_WAIT_LD();
            #pragma unroll
            for (int c = 0; c < 32; ++c) {
                int code = n0 + half * 128 + jj * 32 + c;
                float dot = __uint_as_float(regs[c]);
                float d = __fmaf_rn(-2.f, dot, __fadd_rn(zn, __ldg(&g_enorm[code])));
                if (d < bd2) { bd2 = d; bi2 = code; }
            }
        }
        TC_FENCE_BEFORE();

        cd[(sub * 128 + rl) * 2 + half] = bd2;
        ci[(sub * 128 + rl) * 2 + half] = bi2;
        __syncthreads();

        if (tid < 256) {
            float d0 = cd[tid * 2], d1 = cd[tid * 2 + 1];
            int   i0 = ci[tid * 2], i1 = ci[tid * 2 + 1];
            if (d1 < d0) { d0 = d1; i0 = i1; }   // half0 first => first-index ties
            g_cand_d[n_tile * NROWS + m0 + tid] = d0;
            g_cand_i[n_tile * NROWS + m0 + tid] = i0;
        }
        __syncthreads();
    }

    if (wid == 0) {
        TC_RELINQ();
        TC_DEALLOC(tmem, 512);
    }

#else  // ---------------- fallback: fp32 FFMA2 GEMM-argmin ------------------
    float (*As)[260] = reinterpret_cast<float(*)[260]>(smem);
    float (*Bs)[132] = reinterpret_cast<float(*)[132]>(smem + 33280);

    const int tx = tid & 15;
    const int ty = tid >> 4;
    const int lk = tid & 31;
    const int lm = tid >> 5;

    for (int tile = blockIdx.x; tile < NTILES; tile += GRID_MMA) {
        const int m0 = (tile & (N_MT - 1)) * MT;
        const int n_tile = tile / N_MT;
        const int n0 = n_tile * NT;

        float zn8[8];
        #pragma unroll
        for (int r = 0; r < 8; ++r) zn8[r] = g_znorm[m0 + ty * 8 + r];

        float bestd[8];
        int   besti[8];
        #pragma unroll
        for (int r = 0; r < 8; ++r) { bestd[r] = 3.4e38f; besti[r] = 0; }

        for (int hf = 0; hf < 2; ++hf) {
            const int nb = n0 + hf * 128;
            float2 acc[8][4];
            #pragma unroll
            for (int r = 0; r < 8; ++r)
                #pragma unroll
                for (int j = 0; j < 4; ++j) acc[r][j] = make_float2(0.f, 0.f);

            for (int k0 = 0; k0 < DIM; k0 += 32) {
                __syncthreads();
                #pragma unroll
                for (int j = 0; j < 16; ++j) {
                    int row = lm + j * 16;
                    As[lk][row] = g_zflat[(size_t)(m0 + row) * DIM + k0 + lk];
                }
                #pragma unroll
                for (int j = 0; j < 8; ++j) {
                    int row = lm + j * 16;
                    Bs[lk][row] = emb[(size_t)(nb + row) * DIM + k0 + lk];
                }
                __syncthreads();

                #pragma unroll
                for (int k = 0; k < 32; ++k) {
                    float4 a0 = *reinterpret_cast<const float4*>(&As[k][ty * 8]);
                    float4 a1 = *reinterpret_cast<const float4*>(&As[k][ty * 8 + 4]);
                    float4 b0 = *reinterpret_cast<const float4*>(&Bs[k][tx * 8]);
                    float4 b1 = *reinterpret_cast<const float4*>(&Bs[k][tx * 8 + 4]);
                    unsigned long long bp0 = pack2(b0.x, b0.y);
                    unsigned long long bp1 = pack2(b0.z, b0.w);
                    unsigned long long bp2 = pack2(b1.x, b1.y);
                    unsigned long long bp3 = pack2(b1.z, b1.w);
                    float av[8] = {a0.x, a0.y, a0.z, a0.w, a1.x, a1.y, a1.z, a1.w};
                    #pragma unroll
                    for (int r = 0; r < 8; ++r) {
                        unsigned long long ap = dup2(av[r]);
                        fma2(acc[r][0], ap, bp0);
                        fma2(acc[r][1], ap, bp1);
                        fma2(acc[r][2], ap, bp2);
                        fma2(acc[r][3], ap, bp3);
                    }
                }
            }

            #pragma unroll
            for (int j = 0; j < 8; ++j) {
                int code = nb + tx * 8 + j;
                float en = __ldg(&g_enorm[code]);
                #pragma unroll
                for (int r = 0; r < 8; ++r) {
                    float dot = (j & 1) ? acc[r][j >> 1].y : acc[r][j >> 1].x;
                    float d = __fmaf_rn(-2.f, dot, __fadd_rn(zn8[r], en));
                    if (d < bestd[r]) { bestd[r] = d; besti[r] = code; }
                }
            }
        }

        #pragma unroll
        for (int r = 0; r < 8; ++r) {
            float bd = bestd[r];
            int   bi = besti[r];
            #pragma unroll
            for (int off = 8; off > 0; off >>= 1) {
                float od = __shfl_down_sync(0xffffffffu, bd, off, 16);
                int   oi = __shfl_down_sync(0xffffffffu, bi, off, 16);
                if (od < bd || (od == bd && oi < bi)) { bd = od; bi = oi; }
            }
            if (tx == 0)  {
                int row = m0 + ty * 8 + r;
                g_cand_d[n_tile * NROWS + row] = bd;
                g_cand_i[n_tile * NROWS + row] = bi;
            }
        }
        __syncthreads();
    }
#endif
}

// ---------------------------------------------------------------------------
// K4: merge 64 n-chunks per row (ascending => first-index tie-break)
// ---------------------------------------------------------------------------
__global__ void k_merge(float* __restrict__ out, int out_size) {
    int i = blockIdx.x * blockDim.x + threadIdx.x;
    if (i >= NROWS) return;
    float d0 = g_cand_d[i];
    int   i0 = g_cand_i[i];
    for (int s = 1; s < N_NT; ++s) {
        float d1 = g_cand_d[s * NROWS + i];
        int   i1 = g_cand_i[s * NROWS + i];
        if (d1 < d0) { d0 = d1; i0 = i1; }
    }
    g_idx[i] = i0;
    if (out_size > OFF_IDX + i) out[OFF_IDX + i] = (float)i0;
}

// ---------------------------------------------------------------------------
// K5: gather + straight-through + transpose back + loss partials
// ---------------------------------------------------------------------------
__global__ void k_gather(const float* __restrict__ emb, float* __restrict__ out) {
    __shared__ float red[256];
    int n = blockIdx.x, c = threadIdx.x;
    int b = n >> 10, hw = n & 1023;
    int code = g_idx[n];
    float zf = g_zflat[(size_t)n * DIM + c];
    float zq = emb[(size_t)code * DIM + c];
    float diff = __fsub_rn(zq, zf);
    float st = __fadd_rn(zf, diff);
    out[(size_t)(b * 256 + c) * 1024 + hw] = st;
    red[c] = __fmul_rn(diff, diff);
    __syncthreads();
    #pragma unroll
    for (int s = 128; s > 0; s >>= 1) {
        if (c < s) red[c] = __fadd_rn(red[c], red[c + s]);
        __syncthreads();
    }
    if (c == 0) g_losspart[n] = red[0];
}

__global__ void k_loss(float* __restrict__ out, int out_size) {
    __shared__ float red[256];
    int t = threadIdx.x;
    float s = 0.f;
    for (int i = t; i < NROWS; i += 256) s = __fadd_rn(s, g_losspart[i]);
    red[t] = s;
    __syncthreads();
    #pragma unroll
    for (int k = 128; k > 0; k >>= 1) {
        if (t < k) red[t] = __fadd_rn(red[t], red[t + k]);
        __syncthreads();
    }
    if (t == 0 && out_size > OFF_LOSS)
        out[OFF_LOSS] = 1.25f * red[0] / 2097152.0f;
}

// ---------------------------------------------------------------------------
extern "C" void kernel_launch(void* const* d_in, const int* in_sizes, int n_in,
                              void* d_out, int out_size) {
    const float* z   = (const float*)d_in[0];
    const float* emb = (const float*)d_in[1];
    if (n_in >= 2 && in_sizes[0] == NCODES * DIM && in_sizes[1] == NROWS * DIM) {
        const float* t = z; z = emb; emb = t;
    }
    float* out = (float*)d_out;

    cudaFuncSetAttribute(k_mma, cudaFuncAttributeMaxDynamicSharedMemorySize, SMEM_DYN);

    k_transpose<<<dim3(8, 32, 8), dim3(32, 32)>>>(z);
    k_norms<<<(NROWS + NCODES + 255) / 256, 256>>>(emb);
    k_split_e<<<(NCODES * DIM + 255) / 256, 256>>>(emb);
    k_mma<<<GRID_MMA, 512, SMEM_DYN>>>(emb);
    k_merge<<<NROWS / 256, 256>>>(out, out_size);
    k_gather<<<NROWS, 256>>>(emb, out);
    k_loss<<<1, 256>>>(out, out_size);
}

// round 6
// speedup vs baseline: 5.7813x; 1.9739x over previous
#include <cuda_runtime.h>
#include <cuda_bf16.h>
#include <cstdint>

// ---------------------------------------------------------------------------
// VectorQuantizer. tcgen05 bf16 6-term split GEMM + fused argmin (sm_103a
// pass) with bulk-async (UBLKCP) staged operands and warp-specialized
// producer/consumer; fp32 FFMA2 fallback (baseline sm_103 pass).
// Split operands are PRE-SWIZZLED in gmem as [block128][kc][16KB SW128 tile]
// so each mainloop stage is 2-4 cp.async.bulk instructions (no LDG/STS).
// ---------------------------------------------------------------------------

#if defined(__CUDA_ARCH__) && (defined(__CUDA_ARCH_FEAT_SM103_ALL) || \
    defined(__CUDA_ARCH_FEAT_SM100_ALL) || defined(__CUDA_ARCH_FAMILY_SPECIFIC__))
#define HAS_TC 1
#else
#define HAS_TC 0
#endif

#define NROWS   8192
#define NCODES  16384
#define DIM     256
#define NZQ     2097152
#define OFF_LOSS NZQ
#define OFF_IDX  (NZQ + 1)

#define MT 256
#define NT 256
#define N_MT (NROWS / MT)     // 32
#define N_NT (NCODES / NT)    // 64
#define NTILES (N_MT * N_NT)  // 2048
#define GRID_MMA 148
#define KC 64                 // k per stage
#define STAGES_PER_TILE 24    // 4 kc x 6 terms
#define LOADS_PER_TILE 20     // 5 load-stages per kc

// ---- dynamic smem layout (bytes): A slots 2x32KB, B slots 3x32KB ----
#define SM_A(s)   ((s) * 32768)
#define SM_B(s)   (65536 + (s) * 32768)
#define SM_CD     163840
#define SM_CI     (SM_CD + 2048)
#define SM_TMEMPTR (SM_CI + 2048)
#define SM_MBAR   (SM_TMEMPTR + 8)   // [0,8) mma0 [8,16) mma1 [16,48) tma0..3
#define SMEM_DYN  (SM_MBAR + 64)

// idesc kind::f16: F32 acc(1<<4), A=BF16(1<<7), B=BF16(1<<10), N/8<<17, M/16<<24
#define IDESC 0x8400490u   // M=128, N=256

#define SWZ(o) ((o) ^ (((o) >> 3) & 0x70))

static __device__ __forceinline__ uint32_t smem_u32(const void* p) {
    return (uint32_t)__cvta_generic_to_shared(p);
}

// ---- device scratch ----
__device__ float g_zflat[NROWS * DIM];
__device__ float g_znorm[NROWS];
__device__ float g_enorm[NCODES];
// splits pre-swizzled: [block128][kc(4)][8192 bf16 = 16KB SW128 tile]
__device__ __nv_bfloat16 g_zs0[NROWS * DIM];
__device__ __nv_bfloat16 g_zs1[NROWS * DIM];
__device__ __nv_bfloat16 g_zs2[NROWS * DIM];
__device__ __nv_bfloat16 g_es0[NCODES * DIM];
__device__ __nv_bfloat16 g_es1[NCODES * DIM];
__device__ __nv_bfloat16 g_es2[NCODES * DIM];
__device__ float g_cand_d[N_NT * NROWS];
__device__ int   g_cand_i[N_NT * NROWS];
__device__ int   g_idx[NROWS];
__device__ float g_losspart[NROWS];

// tiled offset for (row n, col c) within a split array (element index)
static __device__ __forceinline__ size_t tiled_off(int n, int c) {
    int blk = n >> 7, r = n & 127, kc = c >> 6, cc = c & 63;
    return ((size_t)((blk << 2) + kc) << 13) + (size_t)r * 64 + (cc ^ ((r & 7) << 3));
}

// ---- packed f32x2 helpers (fallback path) ----
__device__ __forceinline__ unsigned long long pack2(float x, float y) {
    unsigned long long u;
    asm("mov.b64 %0, {%1, %2};" : "=l"(u)
        : "r"(__float_as_uint(x)), "r"(__float_as_uint(y)));
    return u;
}
__device__ __forceinline__ unsigned long long dup2(float x) {
    unsigned long long u;
    unsigned int r = __float_as_uint(x);
    asm("mov.b64 %0, {%1, %1};" : "=l"(u) : "r"(r));
    return u;
}
__device__ __forceinline__ void fma2(float2& d, unsigned long long a, unsigned long long b) {
    unsigned long long* dp = reinterpret_cast<unsigned long long*>(&d);
    asm("fma.rn.f32x2 %0, %1, %2, %0;" : "+l"(*dp) : "l"(a), "l"(b));
}

#if HAS_TC
#define MBAR_INIT(a, c) \
    asm volatile("mbarrier.init.shared.b64 [%0], %1;" :: "r"(a), "r"(c) : "memory")

#define MBAR_WAIT(a, par) do {                                               \
    asm volatile(                                                            \
        "{\n\t.reg .pred P1;\n\t"                                            \
        "WAIT_LOOP_%=:\n\t"                                                  \
        "mbarrier.try_wait.parity.acquire.cta.shared::cta.b64 P1, [%0], %1, 0x989680;\n\t" \
        "@P1 bra.uni WAIT_DONE_%=;\n\t"                                      \
        "bra.uni WAIT_LOOP_%=;\n\t"                                          \
        "WAIT_DONE_%=:\n\t}"                                                 \
        :: "r"(a), "r"(par) : "memory");                                     \
} while (0)

#define MBAR_EXPECT_TX(a, bytes) \
    asm volatile("mbarrier.arrive.expect_tx.shared.b64 _, [%0], %1;" \
                 :: "r"(a), "r"(bytes) : "memory")

#define BULK_G2S(dst, src, sz, mbar) \
    asm volatile("cp.async.bulk.shared::cta.global.mbarrier::complete_tx::bytes " \
                 "[%0], [%1], %2, [%3];" \
                 :: "r"(dst), "l"(src), "r"(sz), "r"(mbar) : "memory")

#define TC_ALLOC(smem_addr, ncols) \
    asm volatile("tcgen05.alloc.cta_group::1.sync.aligned.shared::cta.b32 [%0], %1;" \
                 :: "r"(smem_addr), "r"(ncols) : "memory")
#define TC_DEALLOC(tmem, ncols) \
    asm volatile("tcgen05.dealloc.cta_group::1.sync.aligned.b32 %0, %1;" :: "r"(tmem), "r"(ncols))
#define TC_RELINQ() \
    asm volatile("tcgen05.relinquish_alloc_permit.cta_group::1.sync.aligned;")
#define TC_COMMIT(mbar) \
    asm volatile("tcgen05.commit.cta_group::1.mbarrier::arrive::one.shared::cluster.b64 [%0];" \
                 :: "r"(mbar) : "memory")
#define TC_FENCE_AFTER()  asm volatile("tcgen05.fence::after_thread_sync;" ::: "memory")
#define TC_FENCE_BEFORE() asm volatile("tcgen05.fence::before_thread_sync;" ::: "memory")
#define TC_WAIT_LD()      asm volatile("tcgen05.wait::ld.sync.aligned;" ::: "memory")

static __device__ __forceinline__ void mma_f16_ss(
    uint32_t d_tmem, uint64_t a_desc, uint64_t b_desc, uint32_t idesc, bool acc)
{
    uint32_t en = acc ? 1u : 0u;
    asm volatile(
        "{\n\t.reg .pred p;\n\t"
        "setp.ne.u32 p, %4, 0;\n\t"
        "tcgen05.mma.cta_group::1.kind::f16 [%0], %1, %2, %3, {%5, %5, %5, %5}, p;\n\t"
        "}"
        :: "r"(d_tmem), "l"(a_desc), "l"(b_desc), "r"(idesc), "r"(en), "r"(0u)
        : "memory");
}

#define DESC_BASE ((2ULL << 61) | (1ULL << 46) | (64ULL << 32) | (1ULL << 16))
static __device__ __forceinline__ uint64_t mk_desc(uint32_t addr) {
    return DESC_BASE | ((uint64_t)(addr >> 4) & 0x3FFF);
}

#define LDTM_X32(r, a)                                                        \
    asm volatile("tcgen05.ld.sync.aligned.32x32b.x32.b32 "                    \
        "{%0,%1,%2,%3,%4,%5,%6,%7,%8,%9,%10,%11,%12,%13,%14,%15,"             \
        "%16,%17,%18,%19,%20,%21,%22,%23,%24,%25,%26,%27,%28,%29,%30,%31}, [%32];" \
        : "=r"((r)[0]),"=r"((r)[1]),"=r"((r)[2]),"=r"((r)[3]),                \
          "=r"((r)[4]),"=r"((r)[5]),"=r"((r)[6]),"=r"((r)[7]),                \
          "=r"((r)[8]),"=r"((r)[9]),"=r"((r)[10]),"=r"((r)[11]),              \
          "=r"((r)[12]),"=r"((r)[13]),"=r"((r)[14]),"=r"((r)[15]),            \
          "=r"((r)[16]),"=r"((r)[17]),"=r"((r)[18]),"=r"((r)[19]),            \
          "=r"((r)[20]),"=r"((r)[21]),"=r"((r)[22]),"=r"((r)[23]),            \
          "=r"((r)[24]),"=r"((r)[25]),"=r"((r)[26]),"=r"((r)[27]),            \
          "=r"((r)[28]),"=r"((r)[29]),"=r"((r)[30]),"=r"((r)[31])             \
        : "r"(a))
#endif // HAS_TC

// ---------------------------------------------------------------------------
// K0: transpose z (b,c,h,w) -> zflat[row][c] + bf16 3-split into tiled layout
// ---------------------------------------------------------------------------
__global__ void k_transpose(const float* __restrict__ z) {
    __shared__ float t[32][33];
    int b = blockIdx.z, h = blockIdx.y, c0 = blockIdx.x * 32;
    int tx = threadIdx.x, ty = threadIdx.y;
    t[ty][tx] = z[((size_t)(b * 256 + c0 + ty) * 32 + h) * 32 + tx];
    __syncthreads();
    int n = b * 1024 + h * 32 + ty;
    int c = c0 + tx;
    float x = t[tx][ty];
    g_zflat[(size_t)n * DIM + c] = x;
    __nv_bfloat16 h1 = __float2bfloat16(x);
    float r1 = __fsub_rn(x, __bfloat162float(h1));
    __nv_bfloat16 h2 = __float2bfloat16(r1);
    float r2 = __fsub_rn(r1, __bfloat162float(h2));
    size_t o = tiled_off(n, c);
    g_zs0[o] = h1; g_zs1[o] = h2; g_zs2[o] = __float2bfloat16(r2);
}

// ---------------------------------------------------------------------------
// K1: row norms (reference elementwise square + k-ascending sum rounding)
// ---------------------------------------------------------------------------
__global__ void k_norms(const float* __restrict__ emb) {
    int i = blockIdx.x * blockDim.x + threadIdx.x;
    if (i < NROWS) {
        const float4* p = reinterpret_cast<const float4*>(g_zflat + (size_t)i * DIM);
        float s = 0.f;
        #pragma unroll 8
        for (int c = 0; c < DIM / 4; ++c) {
            float4 v = p[c];
            s = __fadd_rn(s, __fmul_rn(v.x, v.x));
            s = __fadd_rn(s, __fmul_rn(v.y, v.y));
            s = __fadd_rn(s, __fmul_rn(v.z, v.z));
            s = __fadd_rn(s, __fmul_rn(v.w, v.w));
        }
        g_znorm[i] = s;
    } else if (i < NROWS + NCODES) {
        int k = i - NROWS;
        const float4* p = reinterpret_cast<const float4*>(emb + (size_t)k * DIM);
        float s = 0.f;
        #pragma unroll 8
        for (int c = 0; c < DIM / 4; ++c) {
            float4 v = p[c];
            s = __fadd_rn(s, __fmul_rn(v.x, v.x));
            s = __fadd_rn(s, __fmul_rn(v.y, v.y));
            s = __fadd_rn(s, __fmul_rn(v.z, v.z));
            s = __fadd_rn(s, __fmul_rn(v.w, v.w));
        }
        g_enorm[k] = s;
    }
}

// ---------------------------------------------------------------------------
// K2: embedding bf16 3-way split into tiled layout
// ---------------------------------------------------------------------------
__global__ void k_split_e(const float* __restrict__ emb) {
    int i = blockIdx.x * blockDim.x + threadIdx.x;
    if (i >= NCODES * DIM) return;
    int k = i >> 8, c = i & 255;
    float x = emb[i];
    __nv_bfloat16 h1 = __float2bfloat16(x);
    float r1 = __fsub_rn(x, __bfloat162float(h1));
    __nv_bfloat16 h2 = __float2bfloat16(r1);
    float r2 = __fsub_rn(r1, __bfloat162float(h2));
    size_t o = tiled_off(k, c);
    g_es0[o] = h1; g_es1[o] = h2; g_es2[o] = __float2bfloat16(r2);
}

// ---------------------------------------------------------------------------
// K3: persistent GEMM + fused argmin. grid=148, 512 threads.
// Per tile: 4 kc x 6 term-stages. Reuse schedule (A 2 slots X/Y, B 3 slots):
//   j:      0      1      2      3      4      5
//   term:  z1e2   z1e3   z1e1   z2e2   z2e1   z3e1
//   aslot:  X      X      X      Y      Y      X     (X = kc&1)
//   bslot:  0      1      2      0      2      2
//   load:  z1,e2   e3     e1     z2     --     z3
// Every slot overwrite has hazard distance >= 2 stages -> producer waits
// mma_mbar(stage-2). Consumer (tid 0) waits tma mbarriers and issues MMAs;
// producer (tid 32) issues cp.async.bulk copies. No syncthreads in mainloop.
// ---------------------------------------------------------------------------
__global__ __launch_bounds__(512, 1) void k_mma(const float* __restrict__ emb) {
    extern __shared__ char smem[];
    const int tid = threadIdx.x;

#if HAS_TC
    const uint32_t sbase = smem_u32(smem);
    const int wid = tid >> 5;
    const int lane = tid & 31;

    if (wid == 0) TC_ALLOC(sbase + SM_TMEMPTR, 512);
    if (tid == 0) {
        MBAR_INIT(sbase + SM_MBAR, 1);           // mma mbar 0
        MBAR_INIT(sbase + SM_MBAR + 8, 1);       // mma mbar 1
        #pragma unroll
        for (int q = 0; q < 4; ++q)
            MBAR_INIT(sbase + SM_MBAR + 16 + q * 8, 1);   // tma mbars
    }
    __syncthreads();
    uint32_t tmem;
    asm volatile("ld.shared.b32 %0, [%1];" : "=r"(tmem) : "r"(sbase + SM_TMEMPTR));

    const __nv_bfloat16* zsrc[3] = {g_zs0, g_zs1, g_zs2};
    const __nv_bfloat16* esrc[3] = {g_es0, g_es1, g_es2};
    const int tab_as[6] = {0, 0, 0, 1, 1, 0};
    const int tab_bs[6] = {0, 1, 2, 0, 2, 2};
    const int tab_al[6] = {0, -1, -1, 1, -1, 2};
    const int tab_bl[6] = {1, 2, 0, -1, -1, -1};

    float* cd = reinterpret_cast<float*>(smem + SM_CD);
    int*   ci = reinterpret_cast<int*>(smem + SM_CI);

    const int sub  = (wid >> 2) & 1;
    const int half = wid >> 3;
    const int rl   = (wid & 3) * 32 + lane;

    int ti = 0;
    for (int tile = blockIdx.x; tile < NTILES; tile += GRID_MMA, ++ti) {
        const int m0 = (tile & (N_MT - 1)) * MT;
        const int n_tile = tile / N_MT;
        const int n0 = n_tile * NT;
        const int mblk = m0 >> 7;
        const int nblk = n0 >> 7;

        if (tid == 0) {
            // ---- consumer: wait data, issue MMAs ----
            TC_FENCE_AFTER();   // order prev tile's LDTM reads before D overwrite
            int gs = ti * STAGES_PER_TILE;
            int ln = ti * LOADS_PER_TILE;
            for (int s = 0; s < STAGES_PER_TILE; ++s, ++gs) {
                const int kc = s / 6;
                const int j  = s - kc * 6;
                if (j != 4) {
                    MBAR_WAIT(sbase + SM_MBAR + 16 + (ln & 3) * 8, (ln >> 2) & 1);
                    ++ln;
                }
                const int a_slot = tab_as[j] ^ (kc & 1);
                const int b_slot = tab_bs[j];
                uint64_t bd = mk_desc(sbase + SM_B(b_slot));
                #pragma unroll
                for (int sb2 = 0; sb2 < 2; ++sb2) {
                    uint64_t ad = mk_desc(sbase + SM_A(a_slot) + sb2 * 16384);
                    #pragma unroll
                    for (int k = 0; k < 4; ++k)
                        mma_f16_ss(tmem + sb2 * 256, ad + k * 2, bd + k * 2,
                                   IDESC, (s > 0) || (k > 0));
                }
                TC_COMMIT(sbase + SM_MBAR + (gs & 1) * 8);
            }
            // drain: last commit covers all prior MMAs
            int w = gs - 1;
            MBAR_WAIT(sbase + SM_MBAR + (w & 1) * 8, (w >> 1) & 1);
        } else if (tid == 32) {
            // ---- producer: guard slot reuse, issue bulk copies ----
            int gs = ti * STAGES_PER_TILE;
            int ln = ti * LOADS_PER_TILE;
            for (int s = 0; s < STAGES_PER_TILE; ++s, ++gs) {
                const int kc = s / 6;
                const int j  = s - kc * 6;
                if (j == 4) continue;
                if (gs >= 2) {
                    int w = gs - 2;
                    MBAR_WAIT(sbase + SM_MBAR + (w & 1) * 8, (w >> 1) & 1);
                }
                const uint32_t mb = sbase + SM_MBAR + 16 + (ln & 3) * 8;
                const uint32_t bytes = (j == 0) ? 65536u : 32768u;
                MBAR_EXPECT_TX(mb, bytes);
                const int a_slot = tab_as[j] ^ (kc & 1);
                const int b_slot = tab_bs[j];
                if (tab_al[j] >= 0) {
                    const char* src = (const char*)zsrc[tab_al[j]];
                    #pragma unroll
                    for (int sb2 = 0; sb2 < 2; ++sb2)
                        BULK_G2S(sbase + SM_A(a_slot) + sb2 * 16384,
                                 src + ((size_t)((mblk + sb2) * 4 + kc) << 14),
                                 16384u, mb);
                }
                if (tab_bl[j] >= 0) {
                    const char* src = (const char*)esrc[tab_bl[j]];
                    #pragma unroll
                    for (int nb = 0; nb < 2; ++nb)
                        BULK_G2S(sbase + SM_B(b_slot) + nb * 16384,
                                 src + ((size_t)((nblk + nb) * 4 + kc) << 14),
                                 16384u, mb);
                }
                ++ln;
            }
        }
        __syncthreads();       // all MMAs of this tile complete (tid0 drained)
        TC_FENCE_AFTER();

        // ---- epilogue: d = (zn+en) - 2*dot, argmin over 256 codes ----
        const float zn = g_znorm[m0 + sub * 128 + rl];
        float bd2 = 3.4e38f;
        int   bi2 = 0;
        #pragma unroll
        for (int jj = 0; jj < 4; ++jj) {
            uint32_t regs[32];
            LDTM_X32(regs, tmem + sub * 256 + half * 128 + jj * 32);
            TC_WAIT_LD();
            #pragma unroll
            for (int c = 0; c < 32; ++c) {
                int code = n0 + half * 128 + jj * 32 + c;
                float dot = __uint_as_float(regs[c]);
                float d = __fmaf_rn(-2.f, dot, __fadd_rn(zn, __ldg(&g_enorm[code])));
                if (d < bd2) { bd2 = d; bi2 = code; }
            }
        }
        TC_FENCE_BEFORE();

        cd[(sub * 128 + rl) * 2 + half] = bd2;
        ci[(sub * 128 + rl) * 2 + half] = bi2;
        __syncthreads();

        if (tid < 256) {
            float d0 = cd[tid * 2], d1 = cd[tid * 2 + 1];
            int   i0 = ci[tid * 2], i1 = ci[tid * 2 + 1];
            if (d1 < d0) { d0 = d1; i0 = i1; }   // half0 first => first-index ties
            g_cand_d[n_tile * NROWS + m0 + tid] = d0;
            g_cand_i[n_tile * NROWS + m0 + tid] = i0;
        }
        __syncthreads();
    }

    if (wid == 0) {
        TC_RELINQ();
        TC_DEALLOC(tmem, 512);
    }

#else  // ---------------- fallback: fp32 FFMA2 GEMM-argmin ------------------
    float (*As)[260] = reinterpret_cast<float(*)[260]>(smem);
    float (*Bs)[132] = reinterpret_cast<float(*)[132]>(smem + 33280);

    const int tx = tid & 15;
    const int ty = tid >> 4;
    const int lk = tid & 31;
    const int lm = tid >> 5;

    for (int tile = blockIdx.x; tile < NTILES; tile += GRID_MMA) {
        const int m0 = (tile & (N_MT - 1)) * MT;
        const int n_tile = tile / N_MT;
        const int n0 = n_tile * NT;

        float zn8[8];
        #pragma unroll
        for (int r = 0; r < 8; ++r) zn8[r] = g_znorm[m0 + ty * 8 + r];

        float bestd[8];
        int   besti[8];
        #pragma unroll
        for (int r = 0; r < 8; ++r) { bestd[r] = 3.4e38f; besti[r] = 0; }

        for (int hf = 0; hf < 2; ++hf) {
            const int nb = n0 + hf * 128;
            float2 acc[8][4];
            #pragma unroll
            for (int r = 0; r < 8; ++r)
                #pragma unroll
                for (int j = 0; j < 4; ++j) acc[r][j] = make_float2(0.f, 0.f);

            for (int k0 = 0; k0 < DIM; k0 += 32) {
                __syncthreads();
                #pragma unroll
                for (int j = 0; j < 16; ++j) {
                    int row = lm + j * 16;
                    As[lk][row] = g_zflat[(size_t)(m0 + row) * DIM + k0 + lk];
                }
                #pragma unroll
                for (int j = 0; j < 8; ++j) {
                    int row = lm + j * 16;
                    Bs[lk][row] = emb[(size_t)(nb + row) * DIM + k0 + lk];
                }
                __syncthreads();

                #pragma unroll
                for (int k = 0; k < 32; ++k) {
                    float4 a0 = *reinterpret_cast<const float4*>(&As[k][ty * 8]);
                    float4 a1 = *reinterpret_cast<const float4*>(&As[k][ty * 8 + 4]);
                    float4 b0 = *reinterpret_cast<const float4*>(&Bs[k][tx * 8]);
                    float4 b1 = *reinterpret_cast<const float4*>(&Bs[k][tx * 8 + 4]);
                    unsigned long long bp0 = pack2(b0.x, b0.y);
                    unsigned long long bp1 = pack2(b0.z, b0.w);
                    unsigned long long bp2 = pack2(b1.x, b1.y);
                    unsigned long long bp3 = pack2(b1.z, b1.w);
                    float av[8] = {a0.x, a0.y, a0.z, a0.w, a1.x, a1.y, a1.z, a1.w};
                    #pragma unroll
                    for (int r = 0; r < 8; ++r) {
                        unsigned long long ap = dup2(av[r]);
                        fma2(acc[r][0], ap, bp0);
                        fma2(acc[r][1], ap, bp1);
                        fma2(acc[r][2], ap, bp2);
                        fma2(acc[r][3], ap, bp3);
                    }
                }
            }

            #pragma unroll
            for (int j = 0; j < 8; ++j) {
                int code = nb + tx * 8 + j;
                float en = __ldg(&g_enorm[code]);
                #pragma unroll
                for (int r = 0; r < 8; ++r) {
                    float dot = (j & 1) ? acc[r][j >> 1].y : acc[r][j >> 1].x;
                    float d = __fmaf_rn(-2.f, dot, __fadd_rn(zn8[r], en));
                    if (d < bestd[r]) { bestd[r] = d; besti[r] = code; }
                }
            }
        }

        #pragma unroll
        for (int r = 0; r < 8; ++r) {
            float bd = bestd[r];
            int   bi = besti[r];
            #pragma unroll
            for (int off = 8; off > 0; off >>= 1) {
                float od = __shfl_down_sync(0xffffffffu, bd, off, 16);
                int   oi = __shfl_down_sync(0xffffffffu, bi, off, 16);
                if (od < bd || (od == bd && oi < bi)) { bd = od; bi = oi; }
            }
            if (tx == 0) {
                int row = m0 + ty * 8 + r;
                g_cand_d[n_tile * NROWS + row] = bd;
                g_cand_i[n_tile * NROWS + row] = bi;
            }
        }
        __syncthreads();
    }
#endif
}

// ---------------------------------------------------------------------------
// K4: merge 64 n-chunks per row (ascending => first-index tie-break)
// ---------------------------------------------------------------------------
__global__ void k_merge(float* __restrict__ out, int out_size) {
    int i = blockIdx.x * blockDim.x + threadIdx.x;
    if (i >= NROWS) return;
    float d0 = g_cand_d[i];
    int   i0 = g_cand_i[i];
    for (int s = 1; s < N_NT; ++s) {
        float d1 = g_cand_d[s * NROWS + i];
        int   i1 = g_cand_i[s * NROWS + i];
        if (d1 < d0) { d0 = d1; i0 = i1; }
    }
    g_idx[i] = i0;
    if (out_size > OFF_IDX + i) out[OFF_IDX + i] = (float)i0;
}

// ---------------------------------------------------------------------------
// K5: gather + straight-through + transpose back + loss partials
// ---------------------------------------------------------------------------
__global__ void k_gather(const float* __restrict__ emb, float* __restrict__ out) {
    __shared__ float red[256];
    int n = blockIdx.x, c = threadIdx.x;
    int b = n >> 10, hw = n & 1023;
    int code = g_idx[n];
    float zf = g_zflat[(size_t)n * DIM + c];
    float zq = emb[(size_t)code * DIM + c];
    float diff = __fsub_rn(zq, zf);
    float st = __fadd_rn(zf, diff);
    out[(size_t)(b * 256 + c) * 1024 + hw] = st;
    red[c] = __fmul_rn(diff, diff);
    __syncthreads();
    #pragma unroll
    for (int s = 128; s > 0; s >>= 1) {
        if (c < s) red[c] = __fadd_rn(red[c], red[c + s]);
        __syncthreads();
    }
    if (c == 0) g_losspart[n] = red[0];
}

__global__ void k_loss(float* __restrict__ out, int out_size) {
    __shared__ float red[256];
    int t = threadIdx.x;
    float s = 0.f;
    for (int i = t; i < NROWS; i += 256) s = __fadd_rn(s, g_losspart[i]);
    red[t] = s;
    __syncthreads();
    #pragma unroll
    for (int k = 128; k > 0; k >>= 1) {
        if (t < k) red[t] = __fadd_rn(red[t], red[t + k]);
        __syncthreads();
    }
    if (t == 0 && out_size > OFF_LOSS)
        out[OFF_LOSS] = 1.25f * red[0] / 2097152.0f;
}

// ---------------------------------------------------------------------------
extern "C" void kernel_launch(void* const* d_in, const int* in_sizes, int n_in,
                              void* d_out, int out_size) {
    const float* z   = (const float*)d_in[0];
    const float* emb = (const float*)d_in[1];
    if (n_in >= 2 && in_sizes[0] == NCODES * DIM && in_sizes[1] == NROWS * DIM) {
        const float* t = z; z = emb; emb = t;
    }
    float* out = (float*)d_out;

    cudaFuncSetAttribute(k_mma, cudaFuncAttributeMaxDynamicSharedMemorySize, SMEM_DYN);

    k_transpose<<<dim3(8, 32, 8), dim3(32, 32)>>>(z);
    k_norms<<<(NROWS + NCODES + 255) / 256, 256>>>(emb);
    k_split_e<<<(NCODES * DIM + 255) / 256, 256>>>(emb);
    k_mma<<<GRID_MMA, 512, SMEM_DYN>>>(emb);
    k_merge<<<NROWS / 256, 256>>>(out, out_size);
    k_gather<<<NROWS, 256>>>(emb, out);
    k_loss<<<1, 256>>>(out, out_size);
}